// round 9
// baseline (speedup 1.0000x reference)
#include <cuda_runtime.h>
#include <math.h>

// Tropical (max-plus) matmul with exact candidate pruning:
//   out[b,o] = max_i ( W[o,i] + X[b,i] * factors[o] )
// B=512, OUT=1024, IN=1024, fp32.
//
// For f>0 the argmax i must satisfy X[b,i] >= Xmax[b] - (Whi-Wlo)/f_pos_min
// (exact; ~1-3 survivors for N(0,1) X / xavier W). Symmetric bound for f<0;
// f==0, mixed signs, and overflow use exact fallback paths.
//
// Round 9: compute kernel rebuilt as WARP-PER-B with zero block barriers.
// Each warp: 8x LDG.128 X row -> shuffle-only reduce -> per-warp smem
// candidate list (__syncwarp) -> k-outer/j-inner gather loop with 8
// independent LDG.128 per candidate (full MLP) -> 8x STG.128. This removes
// the __syncthreads-chained latency spine that dominated Round 8.

#define B_DIM   512
#define OUT_DIM 1024
#define IN_DIM  1024
#define CAPW    16          // per-warp candidate capacity
#define WARPS_PER_BLK 2

typedef unsigned int u32;

__device__ float g_WT[(size_t)IN_DIM * OUT_DIM];   // WT[i][o] = W[o][i]
// ordered-uint encoded global W extrema; static init = valid bottom/top,
// atomics re-converge to identical values on every graph replay.
__device__ u32   g_whi_key = 0u;
__device__ u32   g_wlo_key = 0xFFFFFFFFu;
__device__ float g_fposmin, g_fnegminabs;

__device__ __forceinline__ u32 fenc(float f) {
    u32 u = __float_as_uint(f);
    return (u & 0x80000000u) ? ~u : (u | 0x80000000u);
}
__device__ __forceinline__ float fdec(u32 k) {
    u32 u = (k & 0x80000000u) ? (k & 0x7FFFFFFFu) : ~k;
    return __uint_as_float(u);
}

// ------- K1: W transpose + global min/max (+ F stats in block (0,0)) ------
__global__ __launch_bounds__(256)
void k_stats_t(const float* __restrict__ W, const float* __restrict__ F)
{
    __shared__ float tile[32][33];
    __shared__ u32 shi[256], slo[256];
    __shared__ float sp[256], sn[256];

    const int tx  = threadIdx.x;         // 0..31
    const int ty  = threadIdx.y;         // 0..7
    const int tid = ty * 32 + tx;
    const int i0  = blockIdx.x * 32;
    const int o0  = blockIdx.y * 32;

    float lmax = -INFINITY, lmin = INFINITY;
    #pragma unroll
    for (int r = ty; r < 32; r += 8) {
        float v = W[(size_t)(o0 + r) * IN_DIM + i0 + tx];
        tile[r][tx] = v;
        lmax = fmaxf(lmax, v);
        lmin = fminf(lmin, v);
    }
    shi[tid] = fenc(lmax);
    slo[tid] = fenc(lmin);

    float fp = INFINITY, fn = INFINITY;
    if (blockIdx.x == 0 && blockIdx.y == 0) {
        #pragma unroll
        for (int j = 0; j < 4; j++) {
            float f = F[tid + j * 256];
            if (f > 0.f) fp = fminf(fp, f);
            if (f < 0.f) fn = fminf(fn, -f);
        }
    }
    sp[tid] = fp; sn[tid] = fn;
    __syncthreads();

    #pragma unroll
    for (int r = ty; r < 32; r += 8)
        g_WT[(size_t)(i0 + r) * OUT_DIM + o0 + tx] = tile[tx][r];

    for (int s = 128; s > 0; s >>= 1) {
        if (tid < s) {
            shi[tid] = max(shi[tid], shi[tid + s]);
            slo[tid] = min(slo[tid], slo[tid + s]);
            sp[tid]  = fminf(sp[tid], sp[tid + s]);
            sn[tid]  = fminf(sn[tid], sn[tid + s]);
        }
        __syncthreads();
    }
    if (tid == 0) {
        atomicMax(&g_whi_key, shi[0]);
        atomicMin(&g_wlo_key, slo[0]);
        if (blockIdx.x == 0 && blockIdx.y == 0) {
            g_fposmin = sp[0]; g_fnegminabs = sn[0];
        }
    }
}

// ---------------- K2: warp-per-b, no block barriers ------------------------
__global__ __launch_bounds__(32 * WARPS_PER_BLK)
void k_warp(const float* __restrict__ X,
            const float* __restrict__ F,
            float* __restrict__ out)
{
    __shared__ int   s_cp[WARPS_PER_BLK], s_cn[WARPS_PER_BLK];
    __shared__ int   s_ci[WARPS_PER_BLK][CAPW];
    __shared__ float s_cx[WARPS_PER_BLK][CAPW];
    __shared__ int   s_cni[WARPS_PER_BLK][CAPW];
    __shared__ float s_cnx[WARPS_PER_BLK][CAPW];

    const int w    = threadIdx.x >> 5;
    const int lane = threadIdx.x & 31;
    const int b    = blockIdx.x * WARPS_PER_BLK + w;

    if (lane == 0) { s_cp[w] = 0; s_cn[w] = 0; }

    // ---- load X row: 8 independent LDG.128 per lane
    const float4* __restrict__ xr4 =
        reinterpret_cast<const float4*>(X + (size_t)b * IN_DIM);
    float4 xv[8];
    #pragma unroll
    for (int j = 0; j < 8; j++) xv[j] = xr4[lane + 32 * j];

    // ---- local max/min tree (float4)
    float4 m4 = xv[0], n4 = xv[0];
    #pragma unroll
    for (int j = 1; j < 8; j++) {
        m4.x = fmaxf(m4.x, xv[j].x); m4.y = fmaxf(m4.y, xv[j].y);
        m4.z = fmaxf(m4.z, xv[j].z); m4.w = fmaxf(m4.w, xv[j].w);
        n4.x = fminf(n4.x, xv[j].x); n4.y = fminf(n4.y, xv[j].y);
        n4.z = fminf(n4.z, xv[j].z); n4.w = fminf(n4.w, xv[j].w);
    }
    float mx = fmaxf(fmaxf(m4.x, m4.y), fmaxf(m4.z, m4.w));
    float mn = fminf(fminf(n4.x, n4.y), fminf(n4.z, n4.w));
    #pragma unroll
    for (int off = 16; off > 0; off >>= 1) {
        mx = fmaxf(mx, __shfl_xor_sync(0xFFFFFFFFu, mx, off));
        mn = fminf(mn, __shfl_xor_sync(0xFFFFFFFFu, mn, off));
    }

    // ---- thresholds (exact, inclusive)
    const float spread = fdec(g_whi_key) - fdec(g_wlo_key);
    const float fpm = g_fposmin, fnm = g_fnegminabs;
    const float tpos = isinf(fpm) ?  INFINITY : mx - spread / fpm;
    const float tneg = isinf(fnm) ? -INFINITY : mn + spread / fnm;

    __syncwarp();   // counters zeroed

    // ---- candidate pushes (rare)
    #pragma unroll
    for (int j = 0; j < 8; j++) {
        const float vals[4] = {xv[j].x, xv[j].y, xv[j].z, xv[j].w};
        #pragma unroll
        for (int c = 0; c < 4; c++) {
            const float v = vals[c];
            if (v >= tpos) {
                int s = atomicAdd(&s_cp[w], 1);
                if (s < CAPW) { s_ci[w][s] = (lane + 32 * j) * 4 + c; s_cx[w][s] = v; }
            }
            if (v <= tneg) {
                int s = atomicAdd(&s_cn[w], 1);
                if (s < CAPW) { s_cni[w][s] = (lane + 32 * j) * 4 + c; s_cnx[w][s] = v; }
            }
        }
    }
    __syncwarp();

    const int cp = s_cp[w], cn = s_cn[w];

    // ---- preload F: 8 float4 per lane (32 outputs)
    const float4* __restrict__ F4 = reinterpret_cast<const float4*>(F);
    float4 f4[8];
    #pragma unroll
    for (int j = 0; j < 8; j++) f4[j] = F4[lane + 32 * j];

    float4 acc[8];
    #pragma unroll
    for (int j = 0; j < 8; j++)
        acc[j] = make_float4(-INFINITY, -INFINITY, -INFINITY, -INFINITY);

    // ---- fast path: pos-candidate loop, k-outer / j-inner (8 indep loads/k)
    const int kend = (cp <= CAPW) ? cp : 0;
    for (int k = 0; k < kend; k++) {
        const float cx = s_cx[w][k];
        const float4* __restrict__ wr4 =
            reinterpret_cast<const float4*>(g_WT + (size_t)s_ci[w][k] * OUT_DIM);
        #pragma unroll
        for (int j = 0; j < 8; j++) {
            const float4 wv = wr4[lane + 32 * j];
            acc[j].x = fmaxf(acc[j].x, fmaf(cx, f4[j].x, wv.x));
            acc[j].y = fmaxf(acc[j].y, fmaf(cx, f4[j].y, wv.y));
            acc[j].z = fmaxf(acc[j].z, fmaf(cx, f4[j].z, wv.z));
            acc[j].w = fmaxf(acc[j].w, fmaf(cx, f4[j].w, wv.w));
        }
    }

    // ---- per-component exact fixup: f<=0, or candidate overflow
    const float* __restrict__ xrow = X + (size_t)b * IN_DIM;
    #pragma unroll
    for (int j = 0; j < 8; j++) {
        float a[4]  = {acc[j].x, acc[j].y, acc[j].z, acc[j].w};
        const float ff[4] = {f4[j].x, f4[j].y, f4[j].z, f4[j].w};
        #pragma unroll
        for (int c = 0; c < 4; c++) {
            const float f = ff[c];
            if (!(f > 0.f && cp <= CAPW)) {
                const int o = (lane + 32 * j) * 4 + c;
                float r = -INFINITY;
                if (f < 0.f && cn <= CAPW) {
                    for (int k = 0; k < cn; k++)
                        r = fmaxf(r, fmaf(s_cnx[w][k], f,
                                   g_WT[(size_t)s_cni[w][k] * OUT_DIM + o]));
                } else {
                    // dense exact fallback (f == 0 or overflow)
                    for (int i = 0; i < IN_DIM; i++)
                        r = fmaxf(r, fmaf(xrow[i], f,
                                   g_WT[(size_t)i * OUT_DIM + o]));
                }
                a[c] = r;
            }
        }
        acc[j] = make_float4(a[0], a[1], a[2], a[3]);
    }

    // ---- store: 8 STG.128
    float4* __restrict__ o4 = reinterpret_cast<float4*>(out + (size_t)b * OUT_DIM);
    #pragma unroll
    for (int j = 0; j < 8; j++) o4[lane + 32 * j] = acc[j];
}

extern "C" void kernel_launch(void* const* d_in, const int* in_sizes, int n_in,
                              void* d_out, int out_size)
{
    const float* X = (const float*)d_in[0];   // (512, 1024)
    const float* W = (const float*)d_in[1];   // (1024, 1024)
    const float* F = (const float*)d_in[2];   // (1024, 1)
    float* out = (float*)d_out;               // (512, 1024)

    dim3 tgrid(IN_DIM / 32, OUT_DIM / 32);    // 32 x 32 = 1024 tiles
    dim3 tblk(32, 8);
    k_stats_t<<<tgrid, tblk>>>(W, F);

    k_warp<<<B_DIM / WARPS_PER_BLK, 32 * WARPS_PER_BLK>>>(X, F, out);
}

// round 10
// speedup vs baseline: 1.1189x; 1.1189x over previous
#include <cuda_runtime.h>
#include <math.h>

// Tropical (max-plus) matmul with exact candidate pruning:
//   out[b,o] = max_i ( W[o,i] + X[b,i] * factors[o] )
// B=512, OUT=1024, IN=1024, fp32.
//
// For f>0 the argmax i must satisfy X[b,i] >= Xmax[b] - (Whi-Wlo)/f_pos_min
// (exact; ~1-3 survivors for N(0,1) X / xavier W). Symmetric bound for f<0;
// f==0, mixed signs, and overflow use exact fallback paths.
//
// Round 10: block-per-b (512 blocks x 256 thr, full co-residency like R8)
// but ZERO block barriers (like R9): every warp redundantly loads the full
// X row (L1 MSHR-merged), shuffle-reduces, builds a private candidate list,
// and computes its own 128 outputs (1 float4/lane -> ~60 regs, 3 blocks/SM).

#define B_DIM   512
#define OUT_DIM 1024
#define IN_DIM  1024
#define CAPW    16          // per-warp candidate capacity
#define NW      8           // warps per block

typedef unsigned int u32;

__device__ float g_WT[(size_t)IN_DIM * OUT_DIM];   // WT[i][o] = W[o][i]
// ordered-uint encoded global W extrema; static init = valid bottom/top,
// atomics re-converge to identical values on every graph replay.
__device__ u32   g_whi_key = 0u;
__device__ u32   g_wlo_key = 0xFFFFFFFFu;
__device__ float g_fposmin, g_fnegminabs;

__device__ __forceinline__ u32 fenc(float f) {
    u32 u = __float_as_uint(f);
    return (u & 0x80000000u) ? ~u : (u | 0x80000000u);
}
__device__ __forceinline__ float fdec(u32 k) {
    u32 u = (k & 0x80000000u) ? (k & 0x7FFFFFFFu) : ~k;
    return __uint_as_float(u);
}

// ------- K1: W transpose + global min/max (+ F stats in block (0,0)) ------
__global__ __launch_bounds__(256)
void k_stats_t(const float* __restrict__ W, const float* __restrict__ F)
{
    __shared__ float tile[32][33];
    __shared__ u32 shi[256], slo[256];
    __shared__ float sp[256], sn[256];

    const int tx  = threadIdx.x;         // 0..31
    const int ty  = threadIdx.y;         // 0..7
    const int tid = ty * 32 + tx;
    const int i0  = blockIdx.x * 32;
    const int o0  = blockIdx.y * 32;

    float lmax = -INFINITY, lmin = INFINITY;
    #pragma unroll
    for (int r = ty; r < 32; r += 8) {
        float v = W[(size_t)(o0 + r) * IN_DIM + i0 + tx];
        tile[r][tx] = v;
        lmax = fmaxf(lmax, v);
        lmin = fminf(lmin, v);
    }
    shi[tid] = fenc(lmax);
    slo[tid] = fenc(lmin);

    float fp = INFINITY, fn = INFINITY;
    if (blockIdx.x == 0 && blockIdx.y == 0) {
        #pragma unroll
        for (int j = 0; j < 4; j++) {
            float f = F[tid + j * 256];
            if (f > 0.f) fp = fminf(fp, f);
            if (f < 0.f) fn = fminf(fn, -f);
        }
    }
    sp[tid] = fp; sn[tid] = fn;
    __syncthreads();

    #pragma unroll
    for (int r = ty; r < 32; r += 8)
        g_WT[(size_t)(i0 + r) * OUT_DIM + o0 + tx] = tile[tx][r];

    for (int s = 128; s > 0; s >>= 1) {
        if (tid < s) {
            shi[tid] = max(shi[tid], shi[tid + s]);
            slo[tid] = min(slo[tid], slo[tid + s]);
            sp[tid]  = fminf(sp[tid], sp[tid + s]);
            sn[tid]  = fminf(sn[tid], sn[tid + s]);
        }
        __syncthreads();
    }
    if (tid == 0) {
        atomicMax(&g_whi_key, shi[0]);
        atomicMin(&g_wlo_key, slo[0]);
        if (blockIdx.x == 0 && blockIdx.y == 0) {
            g_fposmin = sp[0]; g_fnegminabs = sn[0];
        }
    }
}

// ------ K2: block-per-b, barrier-free, warp-autonomous (128 out/warp) ------
__global__ __launch_bounds__(32 * NW, 3)
void k_fused2(const float* __restrict__ X,
              const float* __restrict__ F,
              float* __restrict__ out)
{
    __shared__ int   s_cp[NW], s_cn[NW];
    __shared__ int   s_ci[NW][CAPW];
    __shared__ float s_cx[NW][CAPW];
    __shared__ int   s_cni[NW][CAPW];
    __shared__ float s_cnx[NW][CAPW];

    const int w    = threadIdx.x >> 5;
    const int lane = threadIdx.x & 31;
    const int b    = blockIdx.x;

    if (lane == 0) { s_cp[w] = 0; s_cn[w] = 0; }

    // ---- every warp loads the full X row (MSHR-merged across warps)
    const float4* __restrict__ xr4 =
        reinterpret_cast<const float4*>(X + (size_t)b * IN_DIM);
    float4 xv[8];
    #pragma unroll
    for (int j = 0; j < 8; j++) xv[j] = xr4[lane + 32 * j];

    // ---- shuffle-only max/min reduce
    float4 m4 = xv[0], n4 = xv[0];
    #pragma unroll
    for (int j = 1; j < 8; j++) {
        m4.x = fmaxf(m4.x, xv[j].x); m4.y = fmaxf(m4.y, xv[j].y);
        m4.z = fmaxf(m4.z, xv[j].z); m4.w = fmaxf(m4.w, xv[j].w);
        n4.x = fminf(n4.x, xv[j].x); n4.y = fminf(n4.y, xv[j].y);
        n4.z = fminf(n4.z, xv[j].z); n4.w = fminf(n4.w, xv[j].w);
    }
    float mx = fmaxf(fmaxf(m4.x, m4.y), fmaxf(m4.z, m4.w));
    float mn = fminf(fminf(n4.x, n4.y), fminf(n4.z, n4.w));
    #pragma unroll
    for (int off = 16; off > 0; off >>= 1) {
        mx = fmaxf(mx, __shfl_xor_sync(0xFFFFFFFFu, mx, off));
        mn = fminf(mn, __shfl_xor_sync(0xFFFFFFFFu, mn, off));
    }

    // ---- thresholds (exact, inclusive)
    const float spread = fdec(g_whi_key) - fdec(g_wlo_key);
    const float fpm = g_fposmin, fnm = g_fnegminabs;
    const float tpos = isinf(fpm) ?  INFINITY : mx - spread / fpm;
    const float tneg = isinf(fnm) ? -INFINITY : mn + spread / fnm;

    __syncwarp();   // counters visible

    // ---- candidate pushes into this warp's private list (rare)
    #pragma unroll
    for (int j = 0; j < 8; j++) {
        const float vals[4] = {xv[j].x, xv[j].y, xv[j].z, xv[j].w};
        #pragma unroll
        for (int c = 0; c < 4; c++) {
            const float v = vals[c];
            if (v >= tpos) {
                int s = atomicAdd(&s_cp[w], 1);
                if (s < CAPW) { s_ci[w][s] = (lane + 32 * j) * 4 + c; s_cx[w][s] = v; }
            }
            if (v <= tneg) {
                int s = atomicAdd(&s_cn[w], 1);
                if (s < CAPW) { s_cni[w][s] = (lane + 32 * j) * 4 + c; s_cnx[w][s] = v; }
            }
        }
    }
    __syncwarp();

    const int cp = s_cp[w], cn = s_cn[w];

    // ---- this warp owns outputs [w*128, (w+1)*128): one float4 per lane
    const int o4i = w * 32 + lane;                 // float4 index
    const int o   = o4i * 4;                       // first scalar output
    const float4 f4 = reinterpret_cast<const float4*>(F)[o4i];

    float4 acc = make_float4(-INFINITY, -INFINITY, -INFINITY, -INFINITY);

    // ---- fast path: positive-factor candidate loop (coalesced LDG.128)
    const int kend = (cp <= CAPW) ? cp : 0;
    for (int k = 0; k < kend; k++) {
        const float cx = s_cx[w][k];
        const float4 wv = reinterpret_cast<const float4*>(
            g_WT + (size_t)s_ci[w][k] * OUT_DIM)[o4i];
        acc.x = fmaxf(acc.x, fmaf(cx, f4.x, wv.x));
        acc.y = fmaxf(acc.y, fmaf(cx, f4.y, wv.y));
        acc.z = fmaxf(acc.z, fmaf(cx, f4.z, wv.z));
        acc.w = fmaxf(acc.w, fmaf(cx, f4.w, wv.w));
    }

    // ---- per-component exact fixup: f<=0 or overflow
    {
        float a[4] = {acc.x, acc.y, acc.z, acc.w};
        const float ff[4] = {f4.x, f4.y, f4.z, f4.w};
        const float* __restrict__ xrow = X + (size_t)b * IN_DIM;
        #pragma unroll
        for (int c = 0; c < 4; c++) {
            const float f = ff[c];
            if (!(f > 0.f && cp <= CAPW)) {
                float r = -INFINITY;
                if (f < 0.f && cn <= CAPW) {
                    for (int k = 0; k < cn; k++)
                        r = fmaxf(r, fmaf(s_cnx[w][k], f,
                                   g_WT[(size_t)s_cni[w][k] * OUT_DIM + o + c]));
                } else {
                    // dense exact fallback (f == 0 or overflow)
                    for (int i = 0; i < IN_DIM; i++)
                        r = fmaxf(r, fmaf(xrow[i], f,
                                   g_WT[(size_t)i * OUT_DIM + o + c]));
                }
                a[c] = r;
            }
        }
        acc = make_float4(a[0], a[1], a[2], a[3]);
    }

    reinterpret_cast<float4*>(out + (size_t)b * OUT_DIM)[o4i] = acc;
}

extern "C" void kernel_launch(void* const* d_in, const int* in_sizes, int n_in,
                              void* d_out, int out_size)
{
    const float* X = (const float*)d_in[0];   // (512, 1024)
    const float* W = (const float*)d_in[1];   // (1024, 1024)
    const float* F = (const float*)d_in[2];   // (1024, 1)
    float* out = (float*)d_out;               // (512, 1024)

    dim3 tgrid(IN_DIM / 32, OUT_DIM / 32);    // 32 x 32 = 1024 tiles
    dim3 tblk(32, 8);
    k_stats_t<<<tgrid, tblk>>>(W, F);

    k_fused2<<<B_DIM, 32 * NW>>>(X, F, out);
}

// round 11
// speedup vs baseline: 1.3208x; 1.1805x over previous
#include <cuda_runtime.h>
#include <math.h>

// Tropical (max-plus) matmul with exact candidate pruning, 3-kernel pipeline:
//   out[b,o] = max_i ( W[o,i] + X[b,i] * factors[o] )
// B=512, OUT=1024, IN=1024, fp32.
//
// For f>0 the argmax i must satisfy X[b,i] >= Xmax[b] - (Whi-Wlo)/f_pos_min
// (exact; ~1-3 survivors for N(0,1) X / xavier W). Symmetric bound for f<0;
// f==0, mixed signs, and overflow use exact dense fallbacks.
//
// Round 11: candidate selection hoisted out of the compute kernel (it was
// recomputed per block and dominated the chain). K1: transpose+stats with
// redux.sync reductions. K2: per-b candidates -> global lists (512 blocks).
// K3: trivial gather kernel - no smem, no barriers, ~1 float4 per thread.

#define B_DIM   512
#define OUT_DIM 1024
#define IN_DIM  1024
#define CAP     64

typedef unsigned int u32;

__device__ float g_WT[(size_t)IN_DIM * OUT_DIM];   // WT[i][o] = W[o][i]
// ordered-uint encoded global W extrema; static init = valid bottom/top,
// atomics re-converge to identical values on every graph replay.
__device__ u32   g_whi_key = 0u;
__device__ u32   g_wlo_key = 0xFFFFFFFFu;
__device__ float g_fposmin, g_fnegminabs;

__device__ int   g_cnt_pos[B_DIM], g_cnt_neg[B_DIM];
__device__ int   g_ci_pos[B_DIM][CAP];
__device__ float g_cx_pos[B_DIM][CAP];
__device__ int   g_ci_neg[B_DIM][CAP];
__device__ float g_cx_neg[B_DIM][CAP];

// monotone float <-> uint encoding (float order == unsigned order)
__device__ __forceinline__ u32 fenc(float f) {
    u32 u = __float_as_uint(f);
    return (u & 0x80000000u) ? ~u : (u | 0x80000000u);
}
__device__ __forceinline__ float fdec(u32 k) {
    u32 u = (k & 0x80000000u) ? (k & 0x7FFFFFFFu) : ~k;
    return __uint_as_float(u);
}

// ------- K1: W transpose + global min/max (+ F stats in block (0,0)) ------
__global__ __launch_bounds__(256)
void k_stats_t(const float* __restrict__ W, const float* __restrict__ F)
{
    __shared__ float tile[32][33];
    __shared__ u32 wmax[8], wmin[8], wfp[8], wfn[8];

    const int tx  = threadIdx.x;         // 0..31
    const int ty  = threadIdx.y;         // 0..7
    const int tid = ty * 32 + tx;
    const int lane = tid & 31;
    const int wid  = tid >> 5;
    const int i0  = blockIdx.x * 32;
    const int o0  = blockIdx.y * 32;

    float lmax = -INFINITY, lmin = INFINITY;
    #pragma unroll
    for (int r = ty; r < 32; r += 8) {
        float v = W[(size_t)(o0 + r) * IN_DIM + i0 + tx];
        tile[r][tx] = v;
        lmax = fmaxf(lmax, v);
        lmin = fminf(lmin, v);
    }
    // warp-level redux on monotone keys
    u32 kmax = __reduce_max_sync(0xFFFFFFFFu, fenc(lmax));
    u32 kmin = __reduce_min_sync(0xFFFFFFFFu, fenc(lmin));
    if (lane == 0) { wmax[wid] = kmax; wmin[wid] = kmin; }

    // F stats only in block (0,0): min positive f, min |negative f|
    if (blockIdx.x == 0 && blockIdx.y == 0) {
        float fp = INFINITY, fn = INFINITY;
        #pragma unroll
        for (int j = 0; j < 4; j++) {
            float f = F[tid + j * 256];
            if (f > 0.f) fp = fminf(fp, f);
            if (f < 0.f) fn = fminf(fn, -f);
        }
        u32 kfp = __reduce_min_sync(0xFFFFFFFFu, fenc(fp));
        u32 kfn = __reduce_min_sync(0xFFFFFFFFu, fenc(fn));
        if (lane == 0) { wfp[wid] = kfp; wfn[wid] = kfn; }
    }
    __syncthreads();

    // write transposed tile (coalesced along o)
    #pragma unroll
    for (int r = ty; r < 32; r += 8)
        g_WT[(size_t)(i0 + r) * OUT_DIM + o0 + tx] = tile[tx][r];

    if (tid == 0) {
        u32 hi = wmax[0], lo = wmin[0];
        #pragma unroll
        for (int k = 1; k < 8; k++) {
            hi = max(hi, wmax[k]);
            lo = min(lo, wmin[k]);
        }
        atomicMax(&g_whi_key, hi);
        atomicMin(&g_wlo_key, lo);
        if (blockIdx.x == 0 && blockIdx.y == 0) {
            u32 p = wfp[0], n = wfn[0];
            #pragma unroll
            for (int k = 1; k < 8; k++) {
                p = min(p, wfp[k]);
                n = min(n, wfn[k]);
            }
            g_fposmin    = fdec(p);
            g_fnegminabs = fdec(n);
        }
    }
}

// ------- K2: per-b candidate lists (512 blocks x 256 threads) -------------
__global__ __launch_bounds__(256)
void k_cand(const float* __restrict__ X)
{
    __shared__ u32 wmax[8], wmin[8];
    __shared__ int cp_s, cn_s;
    __shared__ float tpos_s, tneg_s;

    const int b    = blockIdx.x;
    const int tid  = threadIdx.x;
    const int lane = tid & 31;
    const int wid  = tid >> 5;

    if (tid == 0) { cp_s = 0; cn_s = 0; }

    const float4 v4 = reinterpret_cast<const float4*>(X + (size_t)b * IN_DIM)[tid];
    float mx = fmaxf(fmaxf(v4.x, v4.y), fmaxf(v4.z, v4.w));
    float mn = fminf(fminf(v4.x, v4.y), fminf(v4.z, v4.w));
    u32 kmax = __reduce_max_sync(0xFFFFFFFFu, fenc(mx));
    u32 kmin = __reduce_min_sync(0xFFFFFFFFu, fenc(mn));
    if (lane == 0) { wmax[wid] = kmax; wmin[wid] = kmin; }
    __syncthreads();

    if (tid == 0) {
        u32 hi = wmax[0], lo = wmin[0];
        #pragma unroll
        for (int k = 1; k < 8; k++) {
            hi = max(hi, wmax[k]);
            lo = min(lo, wmin[k]);
        }
        const float xmax = fdec(hi), xmin = fdec(lo);
        const float spread = fdec(g_whi_key) - fdec(g_wlo_key);
        const float fpm = g_fposmin, fnm = g_fnegminabs;
        tpos_s = isinf(fpm) ?  INFINITY : xmax - spread / fpm;
        tneg_s = isinf(fnm) ? -INFINITY : xmin + spread / fnm;
    }
    __syncthreads();

    const float tpos = tpos_s, tneg = tneg_s;
    const float vals[4] = {v4.x, v4.y, v4.z, v4.w};
    #pragma unroll
    for (int c = 0; c < 4; c++) {
        const float v = vals[c];
        if (v >= tpos) {
            int s = atomicAdd(&cp_s, 1);
            if (s < CAP) { g_ci_pos[b][s] = 4 * tid + c; g_cx_pos[b][s] = v; }
        }
        if (v <= tneg) {
            int s = atomicAdd(&cn_s, 1);
            if (s < CAP) { g_ci_neg[b][s] = 4 * tid + c; g_cx_neg[b][s] = v; }
        }
    }
    __syncthreads();
    if (tid == 0) { g_cnt_pos[b] = cp_s; g_cnt_neg[b] = cn_s; }
}

// ------- K3: trivial gather compute - no smem, no barriers ----------------
__global__ __launch_bounds__(128)
void k_gather(const float* __restrict__ X,
              const float* __restrict__ F,
              float* __restrict__ out)
{
    const int b   = blockIdx.y;
    const int o4i = blockIdx.x * 128 + threadIdx.x;   // float4 output index
    const int o   = o4i * 4;

    const int cp = g_cnt_pos[b];
    const int cn = g_cnt_neg[b];
    const float4 f4 = reinterpret_cast<const float4*>(F)[o4i];

    float4 acc = make_float4(-INFINITY, -INFINITY, -INFINITY, -INFINITY);

    const bool allpos = (f4.x > 0.f) & (f4.y > 0.f) & (f4.z > 0.f) & (f4.w > 0.f);

    if (allpos && cp <= CAP) {
        for (int k = 0; k < cp; k++) {
            const float cx = g_cx_pos[b][k];                   // uniform (L2)
            const float4 wv = reinterpret_cast<const float4*>(
                g_WT + (size_t)g_ci_pos[b][k] * OUT_DIM)[o4i]; // coalesced
            acc.x = fmaxf(acc.x, fmaf(cx, f4.x, wv.x));
            acc.y = fmaxf(acc.y, fmaf(cx, f4.y, wv.y));
            acc.z = fmaxf(acc.z, fmaf(cx, f4.z, wv.z));
            acc.w = fmaxf(acc.w, fmaf(cx, f4.w, wv.w));
        }
    } else {
        // general exact path per component
        float a[4] = {-INFINITY, -INFINITY, -INFINITY, -INFINITY};
        const float ff[4] = {f4.x, f4.y, f4.z, f4.w};
        const float* __restrict__ xrow = X + (size_t)b * IN_DIM;
        #pragma unroll
        for (int c = 0; c < 4; c++) {
            const float f = ff[c];
            float r = -INFINITY;
            if (f > 0.f && cp <= CAP) {
                for (int k = 0; k < cp; k++)
                    r = fmaxf(r, fmaf(g_cx_pos[b][k], f,
                               g_WT[(size_t)g_ci_pos[b][k] * OUT_DIM + o + c]));
            } else if (f < 0.f && cn <= CAP) {
                for (int k = 0; k < cn; k++)
                    r = fmaxf(r, fmaf(g_cx_neg[b][k], f,
                               g_WT[(size_t)g_ci_neg[b][k] * OUT_DIM + o + c]));
            } else {
                // dense exact fallback (f == 0 or overflow)
                for (int i = 0; i < IN_DIM; i++)
                    r = fmaxf(r, fmaf(xrow[i], f,
                               g_WT[(size_t)i * OUT_DIM + o + c]));
            }
            a[c] = r;
        }
        acc = make_float4(a[0], a[1], a[2], a[3]);
    }

    reinterpret_cast<float4*>(out + (size_t)b * OUT_DIM)[o4i] = acc;
}

extern "C" void kernel_launch(void* const* d_in, const int* in_sizes, int n_in,
                              void* d_out, int out_size)
{
    const float* X = (const float*)d_in[0];   // (512, 1024)
    const float* W = (const float*)d_in[1];   // (1024, 1024)
    const float* F = (const float*)d_in[2];   // (1024, 1)
    float* out = (float*)d_out;               // (512, 1024)

    dim3 tgrid(IN_DIM / 32, OUT_DIM / 32);    // 32 x 32 = 1024 tiles
    dim3 tblk(32, 8);
    k_stats_t<<<tgrid, tblk>>>(W, F);

    k_cand<<<B_DIM, 256>>>(X);

    dim3 ggrid(OUT_DIM / 512, B_DIM);         // (2, 512) = 1024 blocks
    k_gather<<<ggrid, 128>>>(X, F, out);
}